// round 10
// baseline (speedup 1.0000x reference)
#include <cuda_runtime.h>
#include <math.h>

// =====================================================================
// GuidedAttentionL1Loss — fully fused, index-recomputed xpos, Gaussian
// recurrence instead of per-element exp, packed f32x2 arithmetic.
//
// Inputs (metadata order):
//  0 logits  f32 [B,2]
//  1 labels  i32 [B]
//  2 attention_weights f32 [T]
//  3 params  f32 [P]
//  4 xpos    f32 [T]   (UNUSED - recomputed from indices)
//  5 segment_ids i32 [T] (UNUSED - segments are contiguous, starts scanned)
//  6 lengths i32 [B]
// Output: f32 [2] = {loss, nll}
// =====================================================================

#define ABS_BLOCKS 512

__device__ int   g_starts[32768];
__device__ float g_warp_awp[16384];
__device__ float g_abs_part[ABS_BLOCKS];

typedef unsigned long long u64;

__device__ __forceinline__ u64 pk2(float lo, float hi) {
    u64 r; asm("mov.b64 %0, {%1, %2};" : "=l"(r) : "f"(lo), "f"(hi)); return r;
}
__device__ __forceinline__ float hsum2(u64 v) {
    float a, b; asm("mov.b64 {%0, %1}, %2;" : "=f"(a), "=f"(b) : "l"(v)); return a + b;
}
__device__ __forceinline__ u64 add2(u64 a, u64 b) {
    u64 r; asm("add.rn.f32x2 %0, %1, %2;" : "=l"(r) : "l"(a), "l"(b)); return r;
}
__device__ __forceinline__ u64 mul2(u64 a, u64 b) {
    u64 r; asm("mul.rn.f32x2 %0, %1, %2;" : "=l"(r) : "l"(a), "l"(b)); return r;
}
__device__ __forceinline__ u64 fma2(u64 a, u64 b, u64 c) {
    u64 r; asm("fma.rn.f32x2 %0, %1, %2, %3;" : "=l"(r) : "l"(a), "l"(b), "l"(c)); return r;
}

__device__ __forceinline__ float wredsum(float v) {
#pragma unroll
    for (int o = 16; o; o >>= 1) v += __shfl_xor_sync(0xffffffffu, v, o);
    return v;
}

template <bool ALIGNED>
__device__ __forceinline__ float4 ld4(const float* p) {
    if (ALIGNED) return *reinterpret_cast<const float4*>(p);
    float4 v; v.x = p[0]; v.y = p[1]; v.z = p[2]; v.w = p[3]; return v;
}

// ---------------------------------------------------------------------
// Process one segment with one warp. Returns per_seg = sum((w-r)^2)/len.
//
// Math: r = r_hat / (r_sum + 1e-6),  r_hat = exp(-z^2/2)/(std*sqrt(2pi))
//   => r = e / D,  D = (sum e) + 1e-6 * std * sqrt(2pi),  e = exp(-z^2/2)
// sum (w-r)^2 = sum w^2 - 2*sum(w e)/D + sum(e^2)/D^2
//
// z_j = ((j+1) - M) * s,  M = sum(w*(j+1))/sum(w),
//   s = 1e-3 (label==0, std=1000/len) or 1 (label==1, std=1/len).
// ---------------------------------------------------------------------
template <bool ALIGNED>
__device__ __noinline__ float process_segment(const float* __restrict__ ws,
                                              int len, int label, int lane) {
    const int cl = ((len + 127) >> 7) << 2;   // per-lane chunk, multiple of 4
    const int j0 = lane * cl;
    int n = len - j0; if (n < 0) n = 0; if (n > cl) n = cl;
    const int ng = n >> 2, rem = n & 3;
    const float* p = ws + j0;

    // ---- pass 1: sum(w), sum(w*(j+1)), sum(w*w) ----
    u64 A0 = 0, A1 = 0, B0 = 0, B1 = 0, C0 = 0, C1 = 0;
    float fj = (float)(j0 + 1);
    u64 J0 = pk2(fj, fj + 1.f), J1 = pk2(fj + 2.f, fj + 3.f);
    const u64 J4 = pk2(4.f, 4.f);
    for (int g = 0; g < ng; ++g) {
        float4 wv = ld4<ALIGNED>(p + 4 * g);
        u64 W0 = pk2(wv.x, wv.y), W1 = pk2(wv.z, wv.w);
        A0 = add2(A0, W0);        A1 = add2(A1, W1);
        B0 = fma2(W0, J0, B0);    B1 = fma2(W1, J1, B1);
        C0 = fma2(W0, W0, C0);    C1 = fma2(W1, W1, C1);
        J0 = add2(J0, J4);        J1 = add2(J1, J4);
    }
    float s_w  = hsum2(add2(A0, A1));
    float s_wj = hsum2(add2(B0, B1));
    float s_w2 = hsum2(add2(C0, C1));
    for (int t = 0; t < rem; ++t) {
        int j = j0 + (ng << 2) + t;
        float wv = p[(ng << 2) + t];
        s_w += wv; s_wj += wv * (float)(j + 1); s_w2 += wv * wv;
    }
    s_w  = wredsum(s_w);
    s_wj = wredsum(s_wj);
    s_w2 = wredsum(s_w2);

    const float M      = s_wj / s_w;        // weighted mean of (j+1)
    const float invlen = 1.0f / (float)len;

    float se, swe, see, stdv;
    if (label == 1) {
        // std = 1/len => z_j = (j+1) - M (unit spacing). e underflows to
        // exact 0 (same as f32 reference) outside |z| ~ 13.2. A 32-wide
        // window centered on M captures every nonzero e.
        int jlo = (int)floorf(M) - 16;
        int j = jlo + lane;
        bool valid = (j >= 0) && (j < len);
        float t = (float)(j + 1) - M;
        float e  = valid ? __expf(-0.5f * t * t) : 0.0f;
        float wv = valid ? ws[j] : 0.0f;
        se  = wredsum(e);
        swe = wredsum(wv * e);
        see = wredsum(e * e);
        stdv = invlen;                        // MIN_STD / len
    } else {
        // std = 1000/len => z_j = ((j+1)-M)*1e-3 exactly.
        // Gaussian recurrence over each lane's contiguous chunk:
        //   e_{m+4} = e_m * u_m,  u_{m+4} = u_m * rho,  rho = exp(-16 s^2)
        // with s = 1e-3:  arg(e) = -5e-7*t^2,  u = exp(-4e-6*t - 8e-6).
        float tb = (float)(j0 + 1) - M;
        float t0 = tb, t1 = tb + 1.f, t2 = tb + 2.f, t3 = tb + 3.f;
        float e0 = __expf(-5e-7f * t0 * t0);
        float e1 = __expf(-5e-7f * t1 * t1);
        float e2 = __expf(-5e-7f * t2 * t2);
        float e3 = __expf(-5e-7f * t3 * t3);
        float u0 = __expf(fmaf(-4e-6f, t0, -8e-6f));
        float u1 = __expf(fmaf(-4e-6f, t1, -8e-6f));
        float u2 = __expf(fmaf(-4e-6f, t2, -8e-6f));
        float u3 = __expf(fmaf(-4e-6f, t3, -8e-6f));
        u64 E0 = pk2(e0, e1), E1 = pk2(e2, e3);
        u64 U0 = pk2(u0, u1), U1 = pk2(u2, u3);
        const float rho = __expf(-1.6e-5f);
        const u64 R = pk2(rho, rho);
        u64 S0 = 0, S1 = 0, P0 = 0, P1 = 0, Q0 = 0, Q1 = 0;
        for (int g = 0; g < ng; ++g) {
            float4 wv = ld4<ALIGNED>(p + 4 * g);
            u64 W0 = pk2(wv.x, wv.y), W1 = pk2(wv.z, wv.w);
            S0 = add2(S0, E0);        S1 = add2(S1, E1);
            P0 = fma2(W0, E0, P0);    P1 = fma2(W1, E1, P1);
            Q0 = fma2(E0, E0, Q0);    Q1 = fma2(E1, E1, Q1);
            E0 = mul2(E0, U0);        E1 = mul2(E1, U1);
            U0 = mul2(U0, R);         U1 = mul2(U1, R);
        }
        se  = hsum2(add2(S0, S1));
        swe = hsum2(add2(P0, P1));
        see = hsum2(add2(Q0, Q1));
        for (int t = 0; t < rem; ++t) {
            int j = j0 + (ng << 2) + t;
            float wv = p[(ng << 2) + t];
            float tt = (float)(j + 1) - M;
            float e = __expf(-5e-7f * tt * tt);
            se += e; swe += wv * e; see += e * e;
        }
        se  = wredsum(se);
        swe = wredsum(swe);
        see = wredsum(see);
        stdv = 1000.0f * invlen;              // MAX_STD / len
    }

    float D = se + 1e-6f * 2.5066282746310002f * stdv;   // sum(e) + 1e-6/c
    float invD = 1.0f / D;
    float diffsum = s_w2 + (see * invD - 2.0f * swe) * invD;
    return diffsum * invlen;                  // per_seg
}

// ---------------------------------------------------------------------
// Kernel 1: exclusive scan of lengths -> g_starts. One block, 1024 thr.
// ---------------------------------------------------------------------
__global__ void __launch_bounds__(1024) scan_kernel(const int* __restrict__ lengths, int B) {
    __shared__ int wtot[32];
    int tid = threadIdx.x, lane = tid & 31, wid = tid >> 5;
    int ipt = (B + 1023) >> 10;
    int base = tid * ipt;
    int loc = 0;
    for (int k = 0; k < ipt; ++k) { int i = base + k; if (i < B) loc += lengths[i]; }
    int x = loc;
#pragma unroll
    for (int o = 1; o < 32; o <<= 1) {
        int y = __shfl_up_sync(0xffffffffu, x, o);
        if (lane >= o) x += y;
    }
    if (lane == 31) wtot[wid] = x;
    __syncthreads();
    if (wid == 0) {
        int t = wtot[lane];
#pragma unroll
        for (int o = 1; o < 32; o <<= 1) {
            int y = __shfl_up_sync(0xffffffffu, t, o);
            if (lane >= o) t += y;
        }
        wtot[lane] = t;   // inclusive scan of warp totals
    }
    __syncthreads();
    int pre = x - loc + (wid ? wtot[wid - 1] : 0);   // exclusive prefix
    for (int k = 0; k < ipt; ++k) {
        int i = base + k;
        if (i < B) { g_starts[i] = pre; pre += lengths[i]; }
    }
}

// ---------------------------------------------------------------------
// Kernel 2: main. One warp per PAIR of segments (2k, 2k+1) — lengths
// alternate 1024/3072, so each warp gets exactly 4096 elems (balanced).
// ---------------------------------------------------------------------
__global__ void __launch_bounds__(256) main_kernel(const float* __restrict__ attw,
                                                   const int* __restrict__ labels,
                                                   const int* __restrict__ lengths,
                                                   int B, int nwarps) {
    int gw = (blockIdx.x * blockDim.x + threadIdx.x) >> 5;
    int lane = threadIdx.x & 31;
    if (gw >= nwarps) return;
    float acc = 0.f;
#pragma unroll 1
    for (int s = 0; s < 2; ++s) {
        int b = gw * 2 + s;
        if (b < B) {
            int start = g_starts[b];
            int len   = lengths[b];
            int label = labels[b];
            float ps;
            if ((start & 3) == 0)
                ps = process_segment<true >(attw + start, len, label, lane);
            else
                ps = process_segment<false>(attw + start, len, label, lane);
            acc += ps;
        }
    }
    if (lane == 0) g_warp_awp[gw] = acc;
}

// ---------------------------------------------------------------------
// Kernel 3: sum |params| -> block partials (deterministic).
// ---------------------------------------------------------------------
__global__ void __launch_bounds__(256) abs_kernel(const float* __restrict__ p, int P) {
    __shared__ float sred[32];
    int tid = threadIdx.x;
    int gt = blockIdx.x * 256 + tid;
    int stride = gridDim.x * 256;
    int n4 = P >> 2;
    const float4* p4 = reinterpret_cast<const float4*>(p);
    float acc = 0.f;
    for (int i = gt; i < n4; i += stride) {
        float4 v = p4[i];
        acc += fabsf(v.x) + fabsf(v.y) + fabsf(v.z) + fabsf(v.w);
    }
    if (blockIdx.x == 0 && tid == 0)
        for (int i = (n4 << 2); i < P; ++i) acc += fabsf(p[i]);
    acc = wredsum(acc);
    if ((tid & 31) == 0) sred[tid >> 5] = acc;
    __syncthreads();
    if (tid < 32) {
        float v = (tid < 8) ? sred[tid] : 0.f;
        v = wredsum(v);
        if (tid == 0) g_abs_part[blockIdx.x] = v;
    }
}

// ---------------------------------------------------------------------
// Kernel 4: nll + final deterministic reductions + output.
// ---------------------------------------------------------------------
__global__ void __launch_bounds__(1024) final_kernel(const float* __restrict__ logits,
                                                     const int* __restrict__ labels,
                                                     int B, int nwarps,
                                                     float* __restrict__ out) {
    __shared__ float s1[32], s2[32], s3[32];
    int tid = threadIdx.x, lane = tid & 31, wid = tid >> 5;

    float a = 0.f;
    for (int i = tid; i < nwarps; i += 1024) a += g_warp_awp[i];
    float pab = 0.f;
    for (int i = tid; i < ABS_BLOCKS; i += 1024) pab += g_abs_part[i];
    float nl = 0.f;
    for (int i = tid; i < B; i += 1024) {
        float l0 = logits[2 * i], l1 = logits[2 * i + 1];
        int lab = labels[i];
        float m = fmaxf(l0, l1);
        float lse = m + log1pf(__expf(fminf(l0, l1) - m));
        nl += (lab ? l1 : l0) - lse;
    }
    a = wredsum(a); pab = wredsum(pab); nl = wredsum(nl);
    if (lane == 0) { s1[wid] = a; s2[wid] = pab; s3[wid] = nl; }
    __syncthreads();
    if (tid == 0) {
        float A = 0.f, Pa = 0.f, N = 0.f;
        for (int i = 0; i < 32; ++i) { A += s1[i]; Pa += s2[i]; N += s3[i]; }
        float nll     = -N / (float)B;
        float penalty = 5e-5f * Pa;            // ALPHA/2 * sum|p|
        float awp     = 0.5f * A / (float)B;   // BETA/2  * mean(per_seg)
        out[0] = nll + penalty + awp;
        out[1] = nll;
    }
}

// ---------------------------------------------------------------------
extern "C" void kernel_launch(void* const* d_in, const int* in_sizes, int n_in,
                              void* d_out, int out_size) {
    const float* logits  = (const float*)d_in[0];
    const int*   labels  = (const int*)  d_in[1];
    const float* attw    = (const float*)d_in[2];
    const float* params  = (const float*)d_in[3];
    const int*   lengths = (const int*)  d_in[6];

    int B = in_sizes[1];   // labels count
    int P = in_sizes[3];   // params count

    scan_kernel<<<1, 1024>>>(lengths, B);

    int nwarps  = (B + 1) >> 1;
    int nblocks = (nwarps * 32 + 255) / 256;
    if (nblocks > 0)
        main_kernel<<<nblocks, 256>>>(attw, labels, lengths, B, nwarps);

    abs_kernel<<<ABS_BLOCKS, 256>>>(params, P);

    final_kernel<<<1, 1024>>>(logits, labels, B, nwarps, (float*)d_out);
}